// round 1
// baseline (speedup 1.0000x reference)
#include <cuda_runtime.h>
#include <cstdint>

// Problem constants (fixed-shape problem)
#define Bn 16
#define Nn 10000
#define Tn 24
#define Hn 32
#define On 16
#define Mn (Bn*Nn)          // 160000 rows
#define G3H 96              // 3*H

// ---------------- device scratch (no allocations allowed) ----------------
__device__ float g_h   [Mn*Hn];   // GRU output, layout [n][b][32]
__device__ float g_xw1 [Mn*Hn];   // conv1 x@W1,   [n][b][32]
__device__ float g_out1[Mn*Hn];   // conv1 result, [n][b][32]
__device__ float g_xw2 [Mn*On];   // conv2 x@W2,   [n][b][16]
__device__ float g_out2[Mn*On];   // conv2 result, [n][b][16]
__device__ float g_deg [Nn];
__device__ float g_dinv[Nn];

// ---------------- fast activations ----------------
__device__ __forceinline__ float fsig(float x){
    // 1/(1+e^-x); expf->inf handled: 1/inf = 0
    return __fdividef(1.f, 1.f + __expf(-x));
}
__device__ __forceinline__ float ftanh(float x){
    x = fminf(fmaxf(x, -15.f), 15.f);        // avoid inf*0 NaN
    float e = __expf(2.f*x);
    return (e - 1.f) * __fdividef(1.f, e + 1.f);
}

// ---------------- degree / norm ----------------
__global__ void deg_init_kernel(){
    int i = blockIdx.x*blockDim.x + threadIdx.x;
    if (i < Nn) g_deg[i] = 1.f;               // self-loop weight
}
__global__ void deg_acc_kernel(const int* __restrict__ ei,
                               const float* __restrict__ ew, int E){
    int e = blockIdx.x*blockDim.x + threadIdx.x;
    if (e < E) atomicAdd(&g_deg[ei[E + e]], ew[e]);
}
__global__ void dinv_kernel(){
    int i = blockIdx.x*blockDim.x + threadIdx.x;
    if (i < Nn){
        float d = g_deg[i];
        g_dinv[i] = d > 0.f ? rsqrtf(d) : 0.f;
    }
}

// ---------------- GRU: one sequence per thread ----------------
__global__ __launch_bounds__(256,1)
void gru_kernel(const float* __restrict__ x,
                const float* __restrict__ w_ih, const float* __restrict__ w_hh,
                const float* __restrict__ b_ih, const float* __restrict__ b_hh)
{
    __shared__ float s_whh[G3H*Hn];
    __shared__ float s_wih[G3H], s_bih[G3H], s_bhh[G3H];
    int tid = threadIdx.x;
    for (int i = tid; i < G3H*Hn; i += 256) s_whh[i] = w_hh[i];
    if (tid < G3H){ s_wih[tid]=w_ih[tid]; s_bih[tid]=b_ih[tid]; s_bhh[tid]=b_hh[tid]; }
    __syncthreads();

    int m = blockIdx.x*256 + tid;
    if (m >= Mn) return;
    const float* xs = x + (size_t)m * Tn;

    float h[Hn];
#pragma unroll
    for (int k = 0; k < Hn; k++) h[k] = 0.f;

#pragma unroll 1
    for (int t = 0; t < Tn; t++){
        float xt = __ldg(xs + t);
        float hn[Hn];
#pragma unroll
        for (int j = 0; j < Hn; j++){
            float ar0 = s_bhh[j],      ar1 = 0.f;
            float az0 = s_bhh[32+j],   az1 = 0.f;
            float an0 = s_bhh[64+j],   an1 = 0.f;
            const float4* wr = (const float4*)(s_whh +  j      *Hn);
            const float4* wz = (const float4*)(s_whh + (32+j)  *Hn);
            const float4* wn = (const float4*)(s_whh + (64+j)  *Hn);
#pragma unroll
            for (int k4 = 0; k4 < 8; k4++){
                float4 a = wr[k4];
                ar0 += h[4*k4+0]*a.x; ar1 += h[4*k4+1]*a.y;
                ar0 += h[4*k4+2]*a.z; ar1 += h[4*k4+3]*a.w;
            }
#pragma unroll
            for (int k4 = 0; k4 < 8; k4++){
                float4 a = wz[k4];
                az0 += h[4*k4+0]*a.x; az1 += h[4*k4+1]*a.y;
                az0 += h[4*k4+2]*a.z; az1 += h[4*k4+3]*a.w;
            }
#pragma unroll
            for (int k4 = 0; k4 < 8; k4++){
                float4 a = wn[k4];
                an0 += h[4*k4+0]*a.x; an1 += h[4*k4+1]*a.y;
                an0 += h[4*k4+2]*a.z; an1 += h[4*k4+3]*a.w;
            }
            float ar = ar0 + ar1, az = az0 + az1, an = an0 + an1;
            float r  = fsig (xt*s_wih[j]    + s_bih[j]    + ar);
            float z  = fsig (xt*s_wih[32+j] + s_bih[32+j] + az);
            float nv = ftanh(xt*s_wih[64+j] + s_bih[64+j] + r*an);
            hn[j] = nv + z*(h[j] - nv);
        }
#pragma unroll
        for (int j = 0; j < Hn; j++) h[j] = hn[j];
    }

    // write h in [n][b][32] layout for edge-contiguous GCN rows
    int b = m / Nn, n = m % Nn;
    float* dst = g_h + ((size_t)n*Bn + b)*Hn;
#pragma unroll
    for (int k = 0; k < Hn; k += 4)
        *(float4*)(dst + k) = make_float4(h[k], h[k+1], h[k+2], h[k+3]);
}

// ---------------- dense matmul + self-loop init (+ optional bias+relu on input) ----------------
template<int CIN, int COUT, bool RELU>
__global__ void mm_init_kernel(const float* __restrict__ in,
                               const float* __restrict__ W,
                               const float* __restrict__ bin,
                               float* __restrict__ xw,
                               float* __restrict__ outbuf)
{
    __shared__ float sW[CIN*COUT];
    __shared__ float sb[CIN];
    int tid = threadIdx.x;
    for (int i = tid; i < CIN*COUT; i += blockDim.x) sW[i] = W[i];
    if (RELU && tid < CIN) sb[tid] = bin[tid];
    __syncthreads();

    int r = blockIdx.x*blockDim.x + tid;
    if (r >= Mn) return;
    int n = r / Bn;
    float di = g_dinv[n];
    float dd = di*di;                         // self-loop norm

    float v[CIN];
#pragma unroll
    for (int i = 0; i < CIN; i += 4){
        float4 t4 = *(const float4*)(in + (size_t)r*CIN + i);
        v[i]=t4.x; v[i+1]=t4.y; v[i+2]=t4.z; v[i+3]=t4.w;
    }
    if (RELU){
#pragma unroll
        for (int i = 0; i < CIN; i++) v[i] = fmaxf(v[i] + sb[i], 0.f);
    }
    float acc[COUT];
#pragma unroll
    for (int o = 0; o < COUT; o++) acc[o] = 0.f;
#pragma unroll
    for (int i = 0; i < CIN; i++){
        float vi = v[i];
#pragma unroll
        for (int o = 0; o < COUT; o++) acc[o] += vi * sW[i*COUT + o];
    }
    float* px = xw     + (size_t)r*COUT;
    float* po = outbuf + (size_t)r*COUT;
#pragma unroll
    for (int o = 0; o < COUT; o += 4){
        *(float4*)(px+o) = make_float4(acc[o],    acc[o+1],    acc[o+2],    acc[o+3]);
        *(float4*)(po+o) = make_float4(dd*acc[o], dd*acc[o+1], dd*acc[o+2], dd*acc[o+3]);
    }
}

// ---------------- edge scatter: one warp per edge, vectorized fp32 RED ----------------
__device__ __forceinline__ void red4(float* p, float4 v){
    asm volatile("red.global.add.v4.f32 [%0], {%1, %2, %3, %4};"
                 :: "l"(p), "f"(v.x), "f"(v.y), "f"(v.z), "f"(v.w) : "memory");
}

template<int C>
__global__ void scatter_kernel(const int* __restrict__ ei,
                               const float* __restrict__ ew,
                               const float* __restrict__ xw,
                               float* __restrict__ out, int E)
{
    int g    = blockIdx.x*blockDim.x + threadIdx.x;
    int warp = g >> 5;
    int lane = g & 31;
    if (warp >= E) return;

    int src = 0, tgt = 0; float nrm = 0.f;
    if (lane == 0){
        src = ei[warp];
        tgt = ei[E + warp];
        nrm = g_dinv[src] * ew[warp] * g_dinv[tgt];
    }
    src = __shfl_sync(0xffffffffu, src, 0);
    tgt = __shfl_sync(0xffffffffu, tgt, 0);
    nrm = __shfl_sync(0xffffffffu, nrm, 0);

    const float4* s = (const float4*)(xw + (size_t)src*(Bn*C));
    float*        d = out + (size_t)tgt*(Bn*C);
#pragma unroll
    for (int i = 0; i < (Bn*C)/128; i++){
        float4 v = s[lane + 32*i];
        v.x *= nrm; v.y *= nrm; v.z *= nrm; v.w *= nrm;
        red4(d + 4*(lane + 32*i), v);
    }
}

// ---------------- final linear head + [b][n] transpose ----------------
__global__ void final_kernel(const float* __restrict__ b2,
                             const float* __restrict__ Wfc,
                             const float* __restrict__ bfc,
                             float* __restrict__ y)
{
    int r = blockIdx.x*blockDim.x + threadIdx.x;
    if (r >= Mn) return;
    int n = r / Bn, b = r % Bn;
    const float* row = g_out2 + (size_t)r*On;
    float acc = bfc[0];
#pragma unroll
    for (int o = 0; o < On; o++) acc += (row[o] + b2[o]) * Wfc[o];
    y[(size_t)b*Nn + n] = acc;
}

// ---------------- launch ----------------
extern "C" void kernel_launch(void* const* d_in, const int* in_sizes, int n_in,
                              void* d_out, int out_size)
{
    const float* x    = (const float*)d_in[0];
    const int*   ei   = (const int*)  d_in[1];
    const float* ew   = (const float*)d_in[2];
    const float* w_ih = (const float*)d_in[3];
    const float* w_hh = (const float*)d_in[4];
    const float* b_ih = (const float*)d_in[5];
    const float* b_hh = (const float*)d_in[6];
    const float* W1   = (const float*)d_in[7];
    const float* b1   = (const float*)d_in[8];
    const float* W2   = (const float*)d_in[9];
    const float* b2   = (const float*)d_in[10];
    const float* Wfc  = (const float*)d_in[11];
    const float* bfc  = (const float*)d_in[12];
    float* y = (float*)d_out;
    int E = in_sizes[2];

    // resolve __device__ scratch addresses (not an allocation)
    float *p_h, *p_xw1, *p_out1, *p_xw2, *p_out2;
    cudaGetSymbolAddress((void**)&p_h,    g_h);
    cudaGetSymbolAddress((void**)&p_xw1,  g_xw1);
    cudaGetSymbolAddress((void**)&p_out1, g_out1);
    cudaGetSymbolAddress((void**)&p_xw2,  g_xw2);
    cudaGetSymbolAddress((void**)&p_out2, g_out2);

    // 1) gcn_norm
    deg_init_kernel<<<(Nn+255)/256, 256>>>();
    deg_acc_kernel <<<(E +255)/256, 256>>>(ei, ew, E);
    dinv_kernel    <<<(Nn+255)/256, 256>>>();

    // 2) GRU temporal encoder
    gru_kernel<<<Mn/256, 256>>>(x, w_ih, w_hh, b_ih, b_hh);

    // 3) conv1: xw1 = h@W1, out1 init = dinv^2*xw1 (self loop), then edge scatter
    mm_init_kernel<Hn, Hn, false><<<(Mn+127)/128, 128>>>(p_h, W1, nullptr, p_xw1, p_out1);
    scatter_kernel<Hn><<<((size_t)E*32 + 255)/256, 256>>>(ei, ew, p_xw1, p_out1, E);

    // 4) conv2: relu(out1+b1)@W2, self-loop init, edge scatter
    mm_init_kernel<Hn, On, true><<<(Mn+127)/128, 128>>>(p_out1, W2, b1, p_xw2, p_out2);
    scatter_kernel<On><<<((size_t)E*32 + 255)/256, 256>>>(ei, ew, p_xw2, p_out2, E);

    // 5) head: (out2+b2)@Wfc + bfc, transpose to [b][n]
    final_kernel<<<(Mn+255)/256, 256>>>(b2, Wfc, bfc, y);
}